// round 10
// baseline (speedup 1.0000x reference)
#include <cuda_runtime.h>

// Problem constants (shapes fixed by the benchmark instance)
#define W_IN      128
#define UP_FACTOR 8
#define SIZE      (W_IN * UP_FACTOR)   // 1024 interpolated points
#define NTHREADS  256                  // 8 warps/CTA -> 4 warps/SMSP at 2 CTAs/SM
#define NWARP     (NTHREADS / 32)
#define QPT       (SIZE / NTHREADS)    // 4 queries per thread
#define NPAIR     (QPT / 2)            // 2 packed query pairs per thread
#define GRP       16                   // candidates per argmin group
#define NGRP      (SIZE / GRP)         // 64 groups
#define POINT_ORDER_WEIGHT 0.1f

typedef unsigned long long u64;

// ---- Blackwell packed f32x2 helpers (sm_103a) ----
__device__ __forceinline__ u64 pk2(float lo, float hi) {
    u64 r; asm("mov.b64 %0, {%1, %2};" : "=l"(r) : "f"(lo), "f"(hi)); return r;
}
__device__ __forceinline__ u64 fma2(u64 a, u64 b, u64 c) {
    u64 r; asm("fma.rn.f32x2 %0, %1, %2, %3;" : "=l"(r) : "l"(a), "l"(b), "l"(c)); return r;
}
__device__ __forceinline__ void unpk2(u64 v, unsigned &lo, unsigned &hi) {
    asm("mov.b64 {%0, %1}, %2;" : "=r"(lo), "=r"(hi) : "l"(v));
}

// Deterministic per-CTA partials: x = sum(min_dist*m), y = sum(order_pen*m),
// z = sum(direct_err*m) [dir==0 CTAs only]
__device__ float4   g_part[1024];
__device__ unsigned g_done;            // zero-init; reset by last CTA each call

__global__ __launch_bounds__(NTHREADS, 2)
void chamfer_fused_kernel(const float* __restrict__ tgt,
                          const float* __restrict__ pred,
                          const float* __restrict__ vis,
                          float* __restrict__ out,
                          int N)
{
    const int n   = blockIdx.x >> 1;
    const int dir = blockIdx.x & 1;
    const int tid = threadIdx.x;

    __shared__ ulonglong2 sh_cxy[SIZE];    // {(cx,cx),(cy,cy)} per candidate -> LDS.128
    __shared__ u64        sh_cn[SIZE];     // (Cj+B, Cj+B), Cj = cx^2 + cy^2
    __shared__ float2     sh_q[SIZE];      // interpolated queries
    __shared__ float      sh_m[SIZE];      // thresholded mask
    __shared__ unsigned   sh_idx[SIZE];    // raw cn during setup; argmin indices after
    __shared__ float      sh_red[NWARP * 3];
    __shared__ float      sh_B;
    __shared__ int        sh_last;
    __shared__ float      s_f[NTHREADS * 3];   // last-CTA final reduction scratch

    // dir 0: directed(points1=pred, points2=tgt) -> queries = tgt, candidates = pred
    // dir 1: directed(points1=tgt, points2=pred) -> queries = pred, candidates = tgt
    const float* qsrc = (dir == 0) ? tgt  : pred;
    const float* csrc = (dir == 0) ? pred : tgt;
    const float* q0 = qsrc + (size_t)n * (2 * W_IN);
    const float* c0 = csrc + (size_t)n * (2 * W_IN);
    const float* v0 = vis  + (size_t)n * W_IN;

    const float delta = 127.0f / 1023.0f;

    // ---- Interpolation (align_corners=True linear). Track max |q|^2 for B. ----
    float maxSq = 0.0f;
    for (int e = tid; e < SIZE; e += NTHREADS) {
        float pos = (float)e * delta;
        int i0 = (int)pos;
        if (i0 > W_IN - 1) i0 = W_IN - 1;
        int i1 = i0 + 1; if (i1 > W_IN - 1) i1 = W_IN - 1;
        float w  = pos - (float)i0;
        float w0 = 1.0f - w;

        float qx = q0[i0]        * w0 + q0[i1]        * w;
        float qy = q0[W_IN + i0] * w0 + q0[W_IN + i1] * w;
        float cx = c0[i0]        * w0 + c0[i1]        * w;
        float cy = c0[W_IN + i0] * w0 + c0[W_IN + i1] * w;
        float mv = v0[i0]        * w0 + v0[i1]        * w;
        if (mv < 0.5f) mv = 0.0f;

        sh_q[e] = make_float2(qx, qy);
        sh_m[e] = mv;
        sh_cxy[e].x = pk2(cx, cx);
        sh_cxy[e].y = pk2(cy, cy);
        float cn = fmaf(cx, cx, cy * cy);
        sh_idx[e] = __float_as_uint(cn);        // stash raw cn
        float sq = fmaf(qx, qx, qy * qy);
        maxSq = fmaxf(maxSq, sq);
    }
    // CTA max-reduce for the shift constant B
#pragma unroll
    for (int off = 16; off > 0; off >>= 1)
        maxSq = fmaxf(maxSq, __shfl_xor_sync(0xFFFFFFFFu, maxSq, off));
    if ((tid & 31) == 0) sh_red[tid >> 5] = maxSq;
    __syncthreads();
    if (tid == 0) {
        float m = sh_red[0];
#pragma unroll
        for (int w = 1; w < NWARP; w++) m = fmaxf(m, sh_red[w]);
        sh_B = m + 1.0f;
    }
    __syncthreads();
    const float B = sh_B;
    for (int e = tid; e < SIZE; e += NTHREADS) {
        float cnB = __uint_as_float(sh_idx[e]) + B;
        sh_cn[e] = pk2(cnB, cnB);
    }
    __syncthreads();

    // ---- This thread's packed query pairs: queries (tid+2p*256, tid+(2p+1)*256) ----
    u64      m2qx2[NPAIR], m2qy2[NPAIR];
    float    mnL[NPAIR], mnH[NPAIR];        // cumulative running min of d''
    unsigned keyL[NPAIR], keyH[NPAIR];      // (trunc(cummin) | group_id) keys
#pragma unroll
    for (int p = 0; p < NPAIR; p++) {
        float2 a = sh_q[tid + (2 * p) * NTHREADS];
        float2 b = sh_q[tid + (2 * p + 1) * NTHREADS];
        m2qx2[p] = pk2(-2.0f * a.x, -2.0f * b.x);
        m2qy2[p] = pk2(-2.0f * a.y, -2.0f * b.y);
        mnL[p] = __uint_as_float(0x7F7FFFFFu);   // FLT_MAX
        mnH[p] = __uint_as_float(0x7F7FFFFFu);
        keyL[p] = 0xFFFFFFFFu;
        keyH[p] = 0xFFFFFFFFu;
    }

    // ---- Pass 1: grouped scan. d'' = (B + Cj) - 2qx*cx - 2qy*cy >= 1. ----
    // Hot loop per eval: 2 FFMA2 per pair (fma) + 1 FMNMX (alu). Key fold only
    // once per group: trunc monotone => trunc(cummin_g) = min_{j<=end g} trunc(d_j),
    // so min over (trunc(cummin)|g) selects the FIRST group achieving the final
    // trunc-min — the group containing the first global trunc-argmin.
#pragma unroll 1
    for (int g = 0; g < NGRP; g++) {
        const int j0 = g * GRP;
#pragma unroll
        for (int t = 0; t < GRP; t++) {
            ulonglong2 cc = sh_cxy[j0 + t];     // LDS.128 broadcast
            u64 cnB = sh_cn[j0 + t];            // LDS.64 broadcast
#pragma unroll
            for (int p = 0; p < NPAIR; p++) {
                u64 tt = fma2(cc.y, m2qy2[p], cnB);
                u64 d  = fma2(cc.x, m2qx2[p], tt);
                unsigned dl, dh; unpk2(d, dl, dh);
                mnL[p] = fminf(mnL[p], __uint_as_float(dl));   // FMNMX
                mnH[p] = fminf(mnH[p], __uint_as_float(dh));
            }
        }
        const unsigned gu = (unsigned)g;
#pragma unroll
        for (int p = 0; p < NPAIR; p++) {
            keyL[p] = min(keyL[p], (__float_as_uint(mnL[p]) & 0xFFFFFC00u) | gu);
            keyH[p] = min(keyH[p], (__float_as_uint(mnH[p]) & 0xFFFFFC00u) | gu);
        }
    }

    // ---- Pass 2: rescan winning group per query (scalar, identical rounding),
    //      emit exact index, exact-recompute min distance at that index ----
    const float* cf  = (const float*)sh_cxy;   // cx at j*4, cy at j*4+2
    const float* cnf = (const float*)sh_cn;    // cnB at j*2
    float sum_mse = 0.0f;
#pragma unroll
    for (int p = 0; p < NPAIR; p++) {
#pragma unroll
        for (int h = 0; h < 2; h++) {
            const int i = tid + (2 * p + h) * NTHREADS;
            const int g = (int)((h ? keyH[p] : keyL[p]) & 1023u);
            float2 q = sh_q[i];
            float m2qx = -2.0f * q.x;           // identical value to pass-1 operand
            float m2qy = -2.0f * q.y;
            unsigned best = 0xFFFFFFFFu;
            const int j0 = g * GRP;
#pragma unroll
            for (int t = 0; t < GRP; t++) {
                int j = j0 + t;
                float d = fmaf(cf[j * 4], m2qx, fmaf(cf[j * 4 + 2], m2qy, cnf[j * 2]));
                unsigned k = (__float_as_uint(d) & 0xFFFFFC00u) | (unsigned)j;
                best = min(best, k);
            }
            unsigned jsel = best & 1023u;
            sh_idx[i] = jsel;
            // exact distance at selected index
            float dx = q.x - cf[jsel * 4];
            float dy = q.y - cf[jsel * 4 + 2];
            sum_mse += fmaf(dx, dx, dy * dy) * sh_m[i];
        }
    }
    __syncthreads();

    // ---- Index-order penalty + (dir 0) direct error ----
    float sum_ord = 0.0f;
    float sum_dir = 0.0f;
#pragma unroll
    for (int q = 0; q < QPT; q++) {
        int i = tid + q * NTHREADS;
        if (i < SIZE - 1) {
            int   diff = (int)sh_idx[i + 1] - (int)sh_idx[i];
            float nd   = (float)(-diff);
            nd = nd > 0.0f ? nd : 0.0f;             // relu
            sum_ord += nd * nd * sh_m[i];
        }
        if (dir == 0) {
            float2 qv = sh_q[i];
            float dx = qv.x - cf[i * 4];
            float dy = qv.y - cf[i * 4 + 2];
            sum_dir += fmaf(dx, dx, dy * dy) * sh_m[i];
        }
    }

    // ---- CTA reduction (deterministic) ----
#pragma unroll
    for (int off = 16; off > 0; off >>= 1) {
        sum_mse += __shfl_down_sync(0xFFFFFFFFu, sum_mse, off);
        sum_ord += __shfl_down_sync(0xFFFFFFFFu, sum_ord, off);
        sum_dir += __shfl_down_sync(0xFFFFFFFFu, sum_dir, off);
    }
    const int warp = tid >> 5, lane = tid & 31;
    if (lane == 0) {
        sh_red[warp * 3 + 0] = sum_mse;
        sh_red[warp * 3 + 1] = sum_ord;
        sh_red[warp * 3 + 2] = sum_dir;
    }
    __syncthreads();
    if (tid == 0) {
        float a = 0.f, b = 0.f, c = 0.f;
#pragma unroll
        for (int w = 0; w < NWARP; w++) {
            a += sh_red[w * 3 + 0];
            b += sh_red[w * 3 + 1];
            c += sh_red[w * 3 + 2];
        }
        g_part[blockIdx.x] = make_float4(a, b, c, 0.0f);
        __threadfence();
        unsigned ticket = atomicAdd(&g_done, 1u);
        sh_last = (ticket == gridDim.x - 1) ? 1 : 0;
    }
    __syncthreads();

    // ---- Last CTA: global reduce + final formula + counter reset ----
    if (sh_last) {
        __threadfence();                        // acquire all partials
        const int nblocks = gridDim.x;
        float a = 0.f, b = 0.f, c = 0.f;
        for (int i = tid; i < nblocks; i += NTHREADS) {
            float4 p = g_part[i];
            a += p.x; b += p.y; c += p.z;
        }
        s_f[tid] = a; s_f[NTHREADS + tid] = b; s_f[2 * NTHREADS + tid] = c;
        __syncthreads();
        for (int off = NTHREADS / 2; off > 0; off >>= 1) {
            if (tid < off) {
                s_f[tid]                += s_f[tid + off];
                s_f[NTHREADS + tid]     += s_f[NTHREADS + tid + off];
                s_f[2 * NTHREADS + tid] += s_f[2 * NTHREADS + tid + off];
            }
            __syncthreads();
        }
        if (tid == 0) {
            float denom_pts = (float)N * (float)SIZE;
            float matched = s_f[0] / (2.0f * denom_pts)
                          + POINT_ORDER_WEIGHT * s_f[NTHREADS] /
                            (2.0f * (float)N * (float)(SIZE - 1));
            float direct  = s_f[2 * NTHREADS] / denom_pts;
            out[0] = fminf(matched, direct);
            g_done = 0;                         // reset for next (graph) call
        }
    }
}

extern "C" void kernel_launch(void* const* d_in, const int* in_sizes, int n_in,
                              void* d_out, int out_size)
{
    const float* tgt  = (const float*)d_in[0];
    const float* pred = (const float*)d_in[1];
    const float* vis  = (const float*)d_in[2];
    float* out = (float*)d_out;

    const int N = in_sizes[2] / W_IN;     // 128
    const int nblocks = 2 * N;            // 256 CTAs: (batch, direction)

    chamfer_fused_kernel<<<nblocks, NTHREADS>>>(tgt, pred, vis, out, N);
}

// round 11
// speedup vs baseline: 1.5606x; 1.5606x over previous
#include <cuda_runtime.h>

// Problem constants (shapes fixed by the benchmark instance)
#define W_IN      128
#define UP_FACTOR 8
#define SIZE      (W_IN * UP_FACTOR)   // 1024 interpolated points
#define NTHREADS  256                  // 8 warps/CTA, 2 CTAs/SM
#define NWARP     (NTHREADS / 32)
#define QPT       (SIZE / NTHREADS)    // 4 queries per thread (scalar)
#define NPAIRJ    (SIZE / 2)           // 512 candidate pairs
#define GRPP      8                    // candidate PAIRS per group (16 candidates)
#define GRP       (2 * GRPP)           // 16 candidates per group
#define NGRP      (SIZE / GRP)         // 64 groups
#define POINT_ORDER_WEIGHT 0.1f

typedef unsigned long long u64;

// ---- Blackwell packed f32x2 helpers (sm_103a) ----
__device__ __forceinline__ u64 pk2(float lo, float hi) {
    u64 r; asm("mov.b64 %0, {%1, %2};" : "=l"(r) : "f"(lo), "f"(hi)); return r;
}
__device__ __forceinline__ u64 fma2(u64 a, u64 b, u64 c) {
    u64 r; asm("fma.rn.f32x2 %0, %1, %2, %3;" : "=l"(r) : "l"(a), "l"(b), "l"(c)); return r;
}
__device__ __forceinline__ void unpk2(u64 v, unsigned &lo, unsigned &hi) {
    asm("mov.b64 {%0, %1}, %2;" : "=r"(lo), "=r"(hi) : "l"(v));
}

// Deterministic per-CTA partials: x = sum(min_dist*m), y = sum(order_pen*m),
// z = sum(direct_err*m) [dir==0 CTAs only]
__device__ float4   g_part[1024];
__device__ unsigned g_done;            // zero-init; reset by last CTA each call

__global__ __launch_bounds__(NTHREADS, 2)
void chamfer_fused_kernel(const float* __restrict__ tgt,
                          const float* __restrict__ pred,
                          const float* __restrict__ vis,
                          float* __restrict__ out,
                          int N)
{
    const int n   = blockIdx.x >> 1;
    const int dir = blockIdx.x & 1;
    const int tid = threadIdx.x;

    // Candidate pair layout (float view of sh_cxy2):
    //   [j*4+0] = cx_{2j}, [j*4+1] = cx_{2j+1}, [j*4+2] = cy_{2j}, [j*4+3] = cy_{2j+1}
    // sh_cn2 float view: cnf[e] = Ce + B in natural candidate order.
    __shared__ ulonglong2 sh_cxy2[NPAIRJ];  // 8 KB, one LDS.128 = 2 candidates
    __shared__ u64        sh_cn2[NPAIRJ];   // 4 KB, one LDS.64  = 2 candidates
    __shared__ float2     sh_q[SIZE];       // interpolated queries
    __shared__ float      sh_m[SIZE];       // thresholded mask
    __shared__ unsigned   sh_idx[SIZE];     // raw cn stash during setup; indices after
    __shared__ float      sh_red[NWARP * 3];
    __shared__ float      sh_B;
    __shared__ int        sh_last;
    __shared__ float      s_f[NTHREADS * 3];

    // dir 0: directed(points1=pred, points2=tgt) -> queries = tgt, candidates = pred
    // dir 1: directed(points1=tgt, points2=pred) -> queries = pred, candidates = tgt
    const float* qsrc = (dir == 0) ? tgt  : pred;
    const float* csrc = (dir == 0) ? pred : tgt;
    const float* q0 = qsrc + (size_t)n * (2 * W_IN);
    const float* c0 = csrc + (size_t)n * (2 * W_IN);
    const float* v0 = vis  + (size_t)n * W_IN;

    float* cxyf = (float*)sh_cxy2;
    float* cnf  = (float*)sh_cn2;

    const float delta = 127.0f / 1023.0f;

    // ---- Interpolation (align_corners=True linear). Track max |q|^2 for B. ----
    float maxSq = 0.0f;
    for (int e = tid; e < SIZE; e += NTHREADS) {
        float pos = (float)e * delta;
        int i0 = (int)pos;
        if (i0 > W_IN - 1) i0 = W_IN - 1;
        int i1 = i0 + 1; if (i1 > W_IN - 1) i1 = W_IN - 1;
        float w  = pos - (float)i0;
        float w0 = 1.0f - w;

        float qx = q0[i0]        * w0 + q0[i1]        * w;
        float qy = q0[W_IN + i0] * w0 + q0[W_IN + i1] * w;
        float cx = c0[i0]        * w0 + c0[i1]        * w;
        float cy = c0[W_IN + i0] * w0 + c0[W_IN + i1] * w;
        float mv = v0[i0]        * w0 + v0[i1]        * w;
        if (mv < 0.5f) mv = 0.0f;

        sh_q[e] = make_float2(qx, qy);
        sh_m[e] = mv;
        int jp = e >> 1, par = e & 1;
        cxyf[jp * 4 + par]     = cx;
        cxyf[jp * 4 + 2 + par] = cy;
        float cn = fmaf(cx, cx, cy * cy);
        sh_idx[e] = __float_as_uint(cn);        // stash raw cn
        float sq = fmaf(qx, qx, qy * qy);
        maxSq = fmaxf(maxSq, sq);
    }
    // CTA max-reduce for the shift constant B
#pragma unroll
    for (int off = 16; off > 0; off >>= 1)
        maxSq = fmaxf(maxSq, __shfl_xor_sync(0xFFFFFFFFu, maxSq, off));
    if ((tid & 31) == 0) sh_red[tid >> 5] = maxSq;
    __syncthreads();
    if (tid == 0) {
        float m = sh_red[0];
#pragma unroll
        for (int w = 1; w < NWARP; w++) m = fmaxf(m, sh_red[w]);
        sh_B = m + 1.0f;
    }
    __syncthreads();
    const float B = sh_B;
    for (int e = tid; e < SIZE; e += NTHREADS)
        cnf[e] = __uint_as_float(sh_idx[e]) + B;
    __syncthreads();

    // ---- This thread's 4 scalar queries, duplicated-packed operands ----
    u64      m2qx2[QPT], m2qy2[QPT];
    float    mnE[QPT], mnO[QPT];        // cumulative running min, even/odd candidates
    unsigned key[QPT];                  // (trunc(prefix-min) | group_id)
#pragma unroll
    for (int q = 0; q < QPT; q++) {
        float2 v = sh_q[tid + q * NTHREADS];
        m2qx2[q] = pk2(-2.0f * v.x, -2.0f * v.x);
        m2qy2[q] = pk2(-2.0f * v.y, -2.0f * v.y);
        mnE[q] = __uint_as_float(0x7F7FFFFFu);   // FLT_MAX
        mnO[q] = __uint_as_float(0x7F7FFFFFu);
        key[q] = 0xFFFFFFFFu;
    }

    // ---- Pass 1: candidate-pair scan. d'' = (B + Cj) - 2qx*cx - 2qy*cy >= 1. ----
    // One LDS.128 + one LDS.64 serves 2 candidates x 4 queries = 8 evals.
    // Per eval: 1 FFMA2 (fma) + 1 FMNMX (alu). Key fold once per 16-candidate group:
    // trunc monotone => trunc(prefix-min) = prefix-min of trunc'd distances, so the
    // group-key IMNMX selects the first group achieving the global trunc-min, which
    // contains the first global trunc-argmin (first-occurrence semantics preserved).
#pragma unroll 1
    for (int g = 0; g < NGRP; g++) {
        const int p0 = g * GRPP;
#pragma unroll
        for (int t = 0; t < GRPP; t++) {
            ulonglong2 cc = sh_cxy2[p0 + t];    // LDS.128: (cx,cx'),(cy,cy')
            u64 cn2 = sh_cn2[p0 + t];           // LDS.64:  (cnB,cnB')
#pragma unroll
            for (int q = 0; q < QPT; q++) {
                u64 tt = fma2(cc.y, m2qy2[q], cn2);
                u64 d  = fma2(cc.x, m2qx2[q], tt);
                unsigned dl, dh; unpk2(d, dl, dh);
                mnE[q] = fminf(mnE[q], __uint_as_float(dl));   // even candidate
                mnO[q] = fminf(mnO[q], __uint_as_float(dh));   // odd candidate
            }
        }
        const unsigned gu = (unsigned)g;
#pragma unroll
        for (int q = 0; q < QPT; q++) {
            key[q] = min(key[q], (__float_as_uint(mnE[q]) & 0xFFFFFC00u) | gu);
            key[q] = min(key[q], (__float_as_uint(mnO[q]) & 0xFFFFFC00u) | gu);
        }
    }

    // ---- Pass 2: rescan winning 16-candidate group (scalar, identical rounding),
    //      emit exact index, exact-recompute min distance at that index ----
    float sum_mse = 0.0f;
#pragma unroll
    for (int q = 0; q < QPT; q++) {
        const int i = tid + q * NTHREADS;
        const int g = (int)(key[q] & 1023u);
        float2 qv = sh_q[i];
        float m2qx = -2.0f * qv.x;              // identical value to pass-1 operand
        float m2qy = -2.0f * qv.y;
        unsigned best = 0xFFFFFFFFu;
        const int j0 = g * GRP;
#pragma unroll
        for (int t = 0; t < GRP; t++) {
            int j = j0 + t;
            int jp = j >> 1, par = j & 1;
            float cx = cxyf[jp * 4 + par];
            float cy = cxyf[jp * 4 + 2 + par];
            float d = fmaf(cx, m2qx, fmaf(cy, m2qy, cnf[j]));
            unsigned k = (__float_as_uint(d) & 0xFFFFFC00u) | (unsigned)j;
            best = min(best, k);
        }
        unsigned jsel = best & 1023u;
        sh_idx[i] = jsel;
        // exact distance at selected index
        int jp = jsel >> 1, par = jsel & 1;
        float dx = qv.x - cxyf[jp * 4 + par];
        float dy = qv.y - cxyf[jp * 4 + 2 + par];
        sum_mse += fmaf(dx, dx, dy * dy) * sh_m[i];
    }
    __syncthreads();

    // ---- Index-order penalty + (dir 0) direct error ----
    float sum_ord = 0.0f;
    float sum_dir = 0.0f;
#pragma unroll
    for (int q = 0; q < QPT; q++) {
        int i = tid + q * NTHREADS;
        if (i < SIZE - 1) {
            int   diff = (int)sh_idx[i + 1] - (int)sh_idx[i];
            float nd   = (float)(-diff);
            nd = nd > 0.0f ? nd : 0.0f;             // relu
            sum_ord += nd * nd * sh_m[i];
        }
        if (dir == 0) {
            float2 qv = sh_q[i];
            int jp = i >> 1, par = i & 1;
            float dx = qv.x - cxyf[jp * 4 + par];
            float dy = qv.y - cxyf[jp * 4 + 2 + par];
            sum_dir += fmaf(dx, dx, dy * dy) * sh_m[i];
        }
    }

    // ---- CTA reduction (deterministic) ----
#pragma unroll
    for (int off = 16; off > 0; off >>= 1) {
        sum_mse += __shfl_down_sync(0xFFFFFFFFu, sum_mse, off);
        sum_ord += __shfl_down_sync(0xFFFFFFFFu, sum_ord, off);
        sum_dir += __shfl_down_sync(0xFFFFFFFFu, sum_dir, off);
    }
    const int warp = tid >> 5, lane = tid & 31;
    if (lane == 0) {
        sh_red[warp * 3 + 0] = sum_mse;
        sh_red[warp * 3 + 1] = sum_ord;
        sh_red[warp * 3 + 2] = sum_dir;
    }
    __syncthreads();
    if (tid == 0) {
        float a = 0.f, b = 0.f, c = 0.f;
#pragma unroll
        for (int w = 0; w < NWARP; w++) {
            a += sh_red[w * 3 + 0];
            b += sh_red[w * 3 + 1];
            c += sh_red[w * 3 + 2];
        }
        g_part[blockIdx.x] = make_float4(a, b, c, 0.0f);
        __threadfence();
        unsigned ticket = atomicAdd(&g_done, 1u);
        sh_last = (ticket == gridDim.x - 1) ? 1 : 0;
    }
    __syncthreads();

    // ---- Last CTA: global reduce + final formula + counter reset ----
    if (sh_last) {
        __threadfence();                        // acquire all partials
        const int nblocks = gridDim.x;
        float a = 0.f, b = 0.f, c = 0.f;
        for (int i = tid; i < nblocks; i += NTHREADS) {
            float4 p = g_part[i];
            a += p.x; b += p.y; c += p.z;
        }
        s_f[tid] = a; s_f[NTHREADS + tid] = b; s_f[2 * NTHREADS + tid] = c;
        __syncthreads();
        for (int off = NTHREADS / 2; off > 0; off >>= 1) {
            if (tid < off) {
                s_f[tid]                += s_f[tid + off];
                s_f[NTHREADS + tid]     += s_f[NTHREADS + tid + off];
                s_f[2 * NTHREADS + tid] += s_f[2 * NTHREADS + tid + off];
            }
            __syncthreads();
        }
        if (tid == 0) {
            float denom_pts = (float)N * (float)SIZE;
            float matched = s_f[0] / (2.0f * denom_pts)
                          + POINT_ORDER_WEIGHT * s_f[NTHREADS] /
                            (2.0f * (float)N * (float)(SIZE - 1));
            float direct  = s_f[2 * NTHREADS] / denom_pts;
            out[0] = fminf(matched, direct);
            g_done = 0;                         // reset for next (graph) call
        }
    }
}

extern "C" void kernel_launch(void* const* d_in, const int* in_sizes, int n_in,
                              void* d_out, int out_size)
{
    const float* tgt  = (const float*)d_in[0];
    const float* pred = (const float*)d_in[1];
    const float* vis  = (const float*)d_in[2];
    float* out = (float*)d_out;

    const int N = in_sizes[2] / W_IN;     // 128
    const int nblocks = 2 * N;            // 256 CTAs: (batch, direction)

    chamfer_fused_kernel<<<nblocks, NTHREADS>>>(tgt, pred, vis, out, N);
}